// round 9
// baseline (speedup 1.0000x reference)
#include <cuda_runtime.h>
#include <cuda_fp16.h>

// Problem constants
#define T_TOTAL 4096
#define LAYERS  8
#define HIDDEN  1024
#define G4      4096
#define LETTERS 100
#define NCTA    128
#define TPB     256
#define NCELLS  (T_TOTAL * LAYERS)   // 32768
#define SMEM_LAYERS 3
#define WSMEM_BYTES (SMEM_LAYERS * 32 * HIDDEN * 2)   // 196608

// ---------------------------------------------------------------------------
// Device scratch
// ---------------------------------------------------------------------------
__device__ float g_gin[(size_t)T_TOTAL * LAYERS * G4];          // 512 MB input projections
__device__ __half g_w2[(size_t)LAYERS * NCTA * 32 * HIDDEN];    // 64 MB fp16 W_hh, mma A-fragment layout
__device__ __align__(16) float g_c[HIDDEN];                     // final cell state
__device__ unsigned g_fin;                                      // final-round counter

// Seqlock h lines: per CTA two 16B quads {tag, h2x fp16, h2x fp16, pad},
// double-buffered by cell parity. 16B stores/loads are single transactions.
struct __align__(128) HTag { uint4 q[2]; uint4 pad[6]; };
__device__ HTag g_htag[2][NCTA];

__device__ __forceinline__ void ld_acquire_v4(const uint4* p, unsigned& t,
                                              unsigned& a, unsigned& b) {
    unsigned cz;
    asm volatile("ld.acquire.gpu.global.v4.b32 {%0,%1,%2,%3}, [%4];"
                 : "=r"(t), "=r"(a), "=r"(b), "=r"(cz) : "l"(p) : "memory");
}
__device__ __forceinline__ void st_release_v4(uint4* p, unsigned t,
                                              unsigned a, unsigned b) {
    asm volatile("st.release.gpu.global.v4.b32 [%0], {%1,%2,%3,%4};"
                 :: "l"(p), "r"(t), "r"(a), "r"(b), "r"(0u) : "memory");
}
__device__ __forceinline__ unsigned ld_acquire_u32(const unsigned* p) {
    unsigned v;
    asm volatile("ld.acquire.gpu.global.u32 %0, [%1];" : "=r"(v) : "l"(p) : "memory");
    return v;
}
__device__ __forceinline__ void red_release_add(unsigned* p, unsigned v) {
    asm volatile("red.release.gpu.global.add.u32 [%0], %1;" :: "l"(p), "r"(v) : "memory");
}
__device__ __forceinline__ float tanh_approx(float x) {
    float y;
    asm("tanh.approx.f32 %0, %1;" : "=f"(y) : "f"(x));
    return y;
}
__device__ __forceinline__ float sigmoid_fast(float x) {
    return 0.5f + 0.5f * tanh_approx(0.5f * x);
}
__device__ __forceinline__ void mma_16x8x16(float& d0, float& d1, float& d2, float& d3,
                                            uint4 a, unsigned b0, unsigned b1) {
    asm volatile(
        "mma.sync.aligned.m16n8k16.row.col.f32.f16.f16.f32 "
        "{%0,%1,%2,%3}, {%4,%5,%6,%7}, {%8,%9}, {%0,%1,%2,%3};"
        : "+f"(d0), "+f"(d1), "+f"(d2), "+f"(d3)
        : "r"(a.x), "r"(a.y), "r"(a.z), "r"(a.w), "r"(b0), "r"(b1));
}

// ---------------------------------------------------------------------------
// Phase 1a: gin[cell][row] = W_ih@x_t + b_ih + b_hh; reset state.
// ---------------------------------------------------------------------------
__global__ void precompute_kernel(const float* __restrict__ website,
                                  const float* __restrict__ payload,
                                  const float* __restrict__ W_ih,
                                  const float* __restrict__ b_ih,
                                  const float* __restrict__ b_hh) {
    __shared__ float Xsm[16 * LETTERS];
    const int rt = blockIdx.x;
    const int l  = blockIdx.y;
    const int t0 = blockIdx.z * 16;

    for (int idx = threadIdx.x; idx < 16 * LETTERS; idx += 128) {
        int tt = idx / LETTERS, k = idx % LETTERS;
        int t = t0 + tt;
        Xsm[idx] = (t < 2048) ? website[t * LETTERS + k]
                              : payload[(t - 2048) * LETTERS + k];
    }
    __syncthreads();

    const int row = rt * 128 + threadIdx.x;
    const float* wp = W_ih + ((size_t)l * G4 + row) * LETTERS;

    float acc[16];
#pragma unroll
    for (int tt = 0; tt < 16; tt++) acc[tt] = 0.0f;
    for (int k = 0; k < LETTERS; k++) {
        float w = __ldg(wp + k);
#pragma unroll
        for (int tt = 0; tt < 16; tt++) acc[tt] += w * Xsm[tt * LETTERS + k];
    }
    const float bias = b_ih[l * G4 + row] + b_hh[l * G4 + row];
#pragma unroll
    for (int tt = 0; tt < 16; tt++) {
        size_t idx = (((size_t)(t0 + tt)) * LAYERS + l) * G4 + row;
        g_gin[idx] = acc[tt] + bias;
    }

    if (blockIdx.x == 0 && blockIdx.y == 0 && blockIdx.z == 0) {
        // zero both seqlock sets: tag=0, h=0
        if (threadIdx.x < NCTA) {
            uint4 z = {0u, 0u, 0u, 0u};
            g_htag[0][threadIdx.x].q[0] = z;
            g_htag[0][threadIdx.x].q[1] = z;
            g_htag[1][threadIdx.x].q[0] = z;
            g_htag[1][threadIdx.x].q[1] = z;
        }
        if (threadIdx.x == 0) g_fin = 0;
    }
}

// ---------------------------------------------------------------------------
// Phase 1b: repack W_hh fp32 [l][row][k] into mma.m16n8k16 A-fragment layout
// (verified in R8).
// ---------------------------------------------------------------------------
__global__ void repack_whh_kernel(const float* __restrict__ W_hh) {
    size_t idx = (size_t)blockIdx.x * 1024 + threadIdx.x;   // over 8*4096*1024
    int k   = (int)(idx & 1023);
    size_t rowl = idx >> 10;
    int row = (int)(rowl & 4095);
    int l   = (int)(rowl >> 12);

    int g  = row >> 10, rem = row & 1023, bb = rem >> 3, j = rem & 7;
    int r  = g * 8 + j;                 // 0..31
    int mt = r >> 4, rr = r & 15;
    int groupID = rr & 7, rowhalf = rr >> 3;

    int w  = k >> 7, krem = k & 127;
    int kt = krem >> 4, kk = krem & 15;
    int khalf = kk >> 3, tg = (kk & 7) >> 1, oddk = kk & 1;

    int comp = khalf * 2 + rowhalf;     // 0=.x 1=.y 2=.z 3=.w
    int lane = groupID * 4 + tg;
    int t    = mt * 8 + kt;

    size_t base = ((size_t)(l * NCTA) + bb) * 32768;   // halfs per (l,bb)
    size_t dst  = base + ((size_t)(w * 16 + t) * 32 + lane) * 8 + comp * 2 + oddk;
    g_w2[dst] = __float2half(W_hh[idx]);
}

// ---------------------------------------------------------------------------
// Phase 2: persistent recurrent kernel. 128 CTAs x 256 threads.
// Poll = h transport (seqlock). Warp w: 32 rows x K-chunk 128 via 16 HMMA.
// Weight fragments for cell n+1 loaded right after cell n's mma.
// ---------------------------------------------------------------------------
__global__ void __launch_bounds__(TPB, 1)
lstm_kernel(const float* __restrict__ W_lin,
            const float* __restrict__ b_lin,
            const float* __restrict__ W_out,
            const float* __restrict__ b_out,
            float* __restrict__ out) {
    __shared__ __align__(16) __half h_half[HIDDEN];   // fp16 hidden state
    __shared__ float psum_sm[32 * 9];                 // [row][warp], pitch 9
    __shared__ float gin_sm[2][32];
    __shared__ float hn_sm[8];
    __shared__ float feat_sm[16];
    extern __shared__ __align__(16) uint4 w_sm[];     // SMEM_LAYERS * 4096 uint4

    const int tid  = threadIdx.x;
    const int bb   = blockIdx.x;
    const int w    = tid >> 5;
    const int lane = tid & 31;
    const int tg   = lane & 3;
    const int cta_p = tid >> 1;        // polled CTA
    const int k_p   = tid & 1;         // polled quad

    const uint4* __restrict__ wglob = (const uint4*)g_w2;
    const size_t block_u4 = 4096;      // uint4 per (l,bb)

    // ---- copy layers 0..2 of this CTA's weights into smem (once) ----
    for (int l = 0; l < SMEM_LAYERS; l++) {
        const uint4* s = wglob + ((size_t)(l * NCTA) + bb) * block_u4;
#pragma unroll
        for (int i = tid; i < 4096; i += TPB)
            w_sm[l * 4096 + i] = __ldg(&s[i]);
    }
    __syncthreads();

    // ---- prologue: fragments + gin for cell 0 ----
    uint4 wreg[16];
    {
        const uint4* wrow = w_sm + 0 * 4096 + w * 512;   // layer 0 is smem-resident
#pragma unroll
        for (int t = 0; t < 16; t++) wreg[t] = wrow[t * 32 + lane];
    }
    if (tid < 32)
        gin_sm[0][tid] = __ldcs(&g_gin[(size_t)0 * G4
                                       + (tid >> 3) * HIDDEN + bb * 8 + (tid & 7)]);

    float c = 0.0f;   // lane tid<8 of warp 0 owns c[bb*8+tid]

    for (int cell = 0; cell < NCELLS; cell++) {
        const int slot = cell & 1;

        // ---- poll (sync + h transport in one RT), fill h_half ----
        {
            const uint4* p = &g_htag[slot][cta_p].q[k_p];
            unsigned t, a, b;
            ld_acquire_v4(p, t, a, b);
            while (t != (unsigned)cell) ld_acquire_v4(p, t, a, b);
            unsigned* hh = (unsigned*)h_half;
            hh[cta_p * 4 + k_p * 2]     = a;
            hh[cta_p * 4 + k_p * 2 + 1] = b;
        }
        __syncthreads();

        // ---- 16 HMMA per warp: rows 0..31 x K-chunk 128 ----
        float d0[4] = {0.f, 0.f, 0.f, 0.f};
        float d1[4] = {0.f, 0.f, 0.f, 0.f};
        const unsigned* hb = (const unsigned*)h_half;
#pragma unroll
        for (int kt = 0; kt < 8; kt++) {
            const int kbase = w * 128 + kt * 16;
            unsigned b0 = hb[(kbase >> 1) + tg];
            unsigned b1 = hb[(kbase >> 1) + 4 + tg];
            mma_16x8x16(d0[0], d0[1], d0[2], d0[3], wreg[kt], b0, b1);
            mma_16x8x16(d1[0], d1[1], d1[2], d1[3], wreg[8 + kt], b0, b1);
        }

        // ---- prefetch next cell's fragments (drains during reduce/publish/poll) ----
        {
            const int nx = (cell + 1 < NCELLS) ? cell + 1 : 0;
            const int ln = nx & 7;
            if (ln < SMEM_LAYERS) {
                const uint4* wrow = w_sm + ln * 4096 + w * 512;
#pragma unroll
                for (int t = 0; t < 16; t++) wreg[t] = wrow[t * 32 + lane];
            } else {
                const uint4* wrow = wglob + ((size_t)(ln * NCTA) + bb) * block_u4 + w * 512;
#pragma unroll
                for (int t = 0; t < 16; t++) wreg[t] = __ldg(&wrow[t * 32 + lane]);
            }
        }

        // ---- col-0 partials to psum ----
        if (tg == 0) {
            const int gID = lane >> 2;
            psum_sm[(gID) * 9 + w]      = d0[0];
            psum_sm[(gID + 8) * 9 + w]  = d0[2];
            psum_sm[(gID + 16) * 9 + w] = d1[0];
            psum_sm[(gID + 24) * 9 + w] = d1[2];
        }
        __syncthreads();

        // ---- warp 0: gin prefetch (n+1), K-reduce, gates, publish ----
        if (tid < 32) {
            const int nx = (cell + 1 < NCELLS) ? cell + 1 : 0;
            gin_sm[slot ^ 1][tid] = __ldcs(&g_gin[(size_t)nx * G4
                                           + (tid >> 3) * HIDDEN + bb * 8 + (tid & 7)]);

            const float* pr = &psum_sm[lane * 9];
            float s = ((pr[0] + pr[1]) + (pr[2] + pr[3]))
                    + ((pr[4] + pr[5]) + (pr[6] + pr[7]));
            // gather gate sums to lanes 0..7 via shfl
            float v1 = __shfl_sync(0xffffffffu, s, (lane & 7) + 8);
            float v2 = __shfl_sync(0xffffffffu, s, (lane & 7) + 16);
            float v3 = __shfl_sync(0xffffffffu, s, (lane & 7) + 24);
            if (lane < 8) {
                float iv = sigmoid_fast(s  + gin_sm[slot][lane]);
                float fv = sigmoid_fast(v1 + gin_sm[slot][8 + lane]);
                float gv = tanh_approx (v2 + gin_sm[slot][16 + lane]);
                float ov = sigmoid_fast(v3 + gin_sm[slot][24 + lane]);
                c = fv * c + iv * gv;
                hn_sm[lane] = ov * tanh_approx(c);
            }
            __syncwarp();
            if (lane == 0) {
                __half2 p01 = __floats2half2_rn(hn_sm[0], hn_sm[1]);
                __half2 p23 = __floats2half2_rn(hn_sm[2], hn_sm[3]);
                __half2 p45 = __floats2half2_rn(hn_sm[4], hn_sm[5]);
                __half2 p67 = __floats2half2_rn(hn_sm[6], hn_sm[7]);
                const unsigned tagn = (unsigned)(cell + 1);
                HTag* L = &g_htag[slot ^ 1][bb];
                st_release_v4(&L->q[0], tagn, *(unsigned*)&p01, *(unsigned*)&p23);
                st_release_v4(&L->q[1], tagn, *(unsigned*)&p45, *(unsigned*)&p67);
            }
        }
    }

    // ---- publish final c, final-round counter, epilogue on CTA 0 ----
    if (tid < 8) g_c[bb * 8 + tid] = c;
    if (tid < 32) {
        __syncwarp();
        if (tid == 0) {
            __threadfence();
            red_release_add(&g_fin, 1u);
        }
    }

    if (bb == 0) {
        if (tid == 0) {
            while (ld_acquire_u32(&g_fin) < (unsigned)NCTA) { }
        }
        __syncthreads();
        if (tid < 16) {
            const float* wl = W_lin + tid * HIDDEN;
            float a = b_lin[tid];
            for (int k = 0; k < HIDDEN; k++) a += wl[k] * __ldcg(&g_c[k]);
            feat_sm[tid] = a;
        }
        __syncthreads();
        if (tid == 0) {
            float sum = b_out[0];
#pragma unroll
            for (int k = 0; k < 16; k++) sum += W_out[k] * feat_sm[k];
            out[0] = 1.0f / (1.0f + expf(-sum));
        }
    }
}

// ---------------------------------------------------------------------------
// Harness entry. Inputs: 0 website, 1 payload, 2 W_ih, 3 W_hh, 4 b_ih,
// 5 b_hh, 6 W_lin, 7 b_lin, 8 W_out, 9 b_out
// ---------------------------------------------------------------------------
extern "C" void kernel_launch(void* const* d_in, const int* in_sizes, int n_in,
                              void* d_out, int out_size) {
    const float* website = (const float*)d_in[0];
    const float* payload = (const float*)d_in[1];
    const float* W_ih    = (const float*)d_in[2];
    const float* W_hh    = (const float*)d_in[3];
    const float* b_ih    = (const float*)d_in[4];
    const float* b_hh    = (const float*)d_in[5];
    const float* W_lin   = (const float*)d_in[6];
    const float* b_lin   = (const float*)d_in[7];
    const float* W_out   = (const float*)d_in[8];
    const float* b_out   = (const float*)d_in[9];
    float* out = (float*)d_out;

    static int attr_set = 0;
    if (!attr_set) {
        cudaFuncSetAttribute(lstm_kernel,
                             cudaFuncAttributeMaxDynamicSharedMemorySize,
                             WSMEM_BYTES);
        attr_set = 1;
    }

    dim3 grid1(32, 8, 256);
    precompute_kernel<<<grid1, 128>>>(website, payload, W_ih, b_ih, b_hh);
    repack_whh_kernel<<<(LAYERS * G4 * HIDDEN) / 1024, 1024>>>(W_hh);
    lstm_kernel<<<NCTA, TPB, WSMEM_BYTES>>>(W_lin, b_lin, W_out, b_out, out);
}